// round 1
// baseline (speedup 1.0000x reference)
#include <cuda_runtime.h>
#include <cuda_bf16.h>
#include <cstdint>

// Problem constants (from reference)
#define NN 50000   // nodes
#define MM 10000   // hyperedges
#define EE 500000  // incidence pairs
#define DD 128     // feature dim (D_IN = D_OUT = 128)

// ---------------- static scratch (no allocations allowed) ----------------
__device__ float g_xproj[NN * DD];  // 25.6 MB
__device__ float g_esum [MM * DD];  //  5.1 MB
__device__ float g_eproj[MM * DD];  //  5.1 MB
__device__ float g_nsum [NN * DD];  // 25.6 MB
__device__ int   g_ecnt [MM];
__device__ int   g_ncnt [NN];
__device__ int   g_colmin;

// ---------------- init: zero accumulators, reset colmin ----------------
__global__ void k_init() {
    int i = blockIdx.x * blockDim.x + threadIdx.x;
    int stride = gridDim.x * blockDim.x;
    for (int j = i; j < NN * DD; j += stride) g_nsum[j] = 0.0f;
    for (int j = i; j < MM * DD; j += stride) g_esum[j] = 0.0f;
    for (int j = i; j < NN; j += stride) g_ncnt[j] = 0;
    for (int j = i; j < MM; j += stride) g_ecnt[j] = 0;
    if (i == 0) g_colmin = 0x7fffffff;
}

// ---------------- col min reduction ----------------
__global__ void k_colmin(const int* __restrict__ col, int E) {
    int v = 0x7fffffff;
    for (int j = blockIdx.x * blockDim.x + threadIdx.x; j < E;
         j += gridDim.x * blockDim.x)
        v = min(v, col[j]);
#pragma unroll
    for (int o = 16; o > 0; o >>= 1) v = min(v, __shfl_down_sync(0xffffffffu, v, o));
    if ((threadIdx.x & 31) == 0) atomicMin(&g_colmin, v);
}

// ---------------- vector float atomic add (sm_90+) ----------------
__device__ __forceinline__ void red_add_v4(float* p, float4 v) {
    asm volatile("red.global.add.v4.f32 [%0], {%1,%2,%3,%4};"
                 :: "l"(p), "f"(v.x), "f"(v.y), "f"(v.z), "f"(v.w)
                 : "memory");
}

// ---------------- scatter 1: node features -> hyperedge sums ----------------
__global__ void k_scatter1(const int* __restrict__ row, const int* __restrict__ col, int E) {
    const int cmin = g_colmin;
    const int lane = threadIdx.x & 31;
    const int warp = (blockIdx.x * blockDim.x + threadIdx.x) >> 5;
    const int nw   = (gridDim.x * blockDim.x) >> 5;
    for (int e = warp; e < E; e += nw) {
        int r = __ldg(&row[e]);
        int c = __ldg(&col[e]) - cmin;
        float4 v = *(const float4*)&g_xproj[(size_t)r * DD + lane * 4];
        red_add_v4(&g_esum[(size_t)c * DD + lane * 4], v);
        if (lane == 0) atomicAdd(&g_ecnt[c], 1);
    }
}

// ---------------- scatter 2: hyperedge features -> node sums ----------------
__global__ void k_scatter2(const int* __restrict__ row, const int* __restrict__ col, int E) {
    const int cmin = g_colmin;
    const int lane = threadIdx.x & 31;
    const int warp = (blockIdx.x * blockDim.x + threadIdx.x) >> 5;
    const int nw   = (gridDim.x * blockDim.x) >> 5;
    for (int e = warp; e < E; e += nw) {
        int r = __ldg(&row[e]);
        int c = __ldg(&col[e]) - cmin;
        float4 v = *(const float4*)&g_eproj[(size_t)c * DD + lane * 4];
        red_add_v4(&g_nsum[(size_t)r * DD + lane * 4], v);
        if (lane == 0) atomicAdd(&g_ncnt[r], 1);
    }
}

// ---------------- SGEMM: C[Mrows x 128] = A[Mrows x K] @ B[K x 128] ----------------
// HAS_A1: K=256, k in [0,128) from A0, k in [128,256) from A1
// SCALE0: A0 rows scaled by 1/max(cnt0[row],1)   (for segment mean)
// SCALE1: A1 rows scaled by 1/max(cnt1[row],1)
// EPI:    C = relu(C + bias)
template <bool HAS_A1, bool SCALE0, bool SCALE1, bool EPI>
__global__ void __launch_bounds__(256, 2) k_gemm(
    const float* __restrict__ A0, const float* __restrict__ A1,
    const int* __restrict__ cnt0, const int* __restrict__ cnt1,
    const float* __restrict__ Bm, const float* __restrict__ bias,
    float* __restrict__ C, int Mrows)
{
    constexpr int K = HAS_A1 ? 256 : 128;
    __shared__ float As[16][132];  // padded
    __shared__ float Bs[16][128];

    const int tid = threadIdx.x;
    const int ty = tid >> 4;   // 0..15
    const int tx = tid & 15;   // 0..15
    const int rowBase = blockIdx.x * 128;

    float acc[8][8];
#pragma unroll
    for (int i = 0; i < 8; i++)
#pragma unroll
        for (int j = 0; j < 8; j++) acc[i][j] = 0.0f;

    const int aRow = tid >> 2;        // 0..63
    const int aCol = (tid & 3) << 2;  // 0,4,8,12
    const int bRow = tid >> 5;        // 0..7
    const int bCol = (tid & 31) << 2; // 0..124

#pragma unroll
    for (int kb = 0; kb < K; kb += 16) {
        const bool second = HAS_A1 && (kb >= 128);
        const float* Aptr = second ? A1 : A0;
        const int kOff = second ? (kb - 128) : kb;

        // load A tile (128 x 16), transposed into As[k][m]
#pragma unroll
        for (int p = 0; p < 2; p++) {
            int r = aRow + p * 64;
            int gr = rowBase + r;
            float4 v = make_float4(0.f, 0.f, 0.f, 0.f);
            if (gr < Mrows) {
                v = *(const float4*)&Aptr[(size_t)gr * DD + kOff + aCol];
                if ((SCALE0 && !second) || (SCALE1 && second)) {
                    const int* cp = second ? cnt1 : cnt0;
                    float s = 1.0f / fmaxf((float)__ldg(&cp[gr]), 1.0f);
                    v.x *= s; v.y *= s; v.z *= s; v.w *= s;
                }
            }
            As[aCol + 0][r] = v.x;
            As[aCol + 1][r] = v.y;
            As[aCol + 2][r] = v.z;
            As[aCol + 3][r] = v.w;
        }
        // load B tile (16 x 128)
#pragma unroll
        for (int p = 0; p < 2; p++) {
            int kr = bRow + p * 8;
            float4 v = *(const float4*)&Bm[(size_t)(kb + kr) * DD + bCol];
            *(float4*)&Bs[kr][bCol] = v;
        }
        __syncthreads();

#pragma unroll
        for (int k = 0; k < 16; k++) {
            float ar[8], br[8];
            *(float4*)&ar[0] = *(const float4*)&As[k][ty * 8];
            *(float4*)&ar[4] = *(const float4*)&As[k][ty * 8 + 4];
            *(float4*)&br[0] = *(const float4*)&Bs[k][tx * 8];
            *(float4*)&br[4] = *(const float4*)&Bs[k][tx * 8 + 4];
#pragma unroll
            for (int i = 0; i < 8; i++)
#pragma unroll
                for (int j = 0; j < 8; j++)
                    acc[i][j] = fmaf(ar[i], br[j], acc[i][j]);
        }
        __syncthreads();
    }

    // epilogue
#pragma unroll
    for (int i = 0; i < 8; i++) {
        int gr = rowBase + ty * 8 + i;
        if (gr < Mrows) {
#pragma unroll
            for (int j = 0; j < 8; j += 4) {
                int gc = tx * 8 + j;
                float4 v = make_float4(acc[i][j], acc[i][j + 1], acc[i][j + 2], acc[i][j + 3]);
                if (EPI) {
                    v.x = fmaxf(v.x + bias[gc + 0], 0.0f);
                    v.y = fmaxf(v.y + bias[gc + 1], 0.0f);
                    v.z = fmaxf(v.z + bias[gc + 2], 0.0f);
                    v.w = fmaxf(v.w + bias[gc + 3], 0.0f);
                }
                *(float4*)&C[(size_t)gr * DD + gc] = v;
            }
        }
    }
}

// ---------------- launch ----------------
extern "C" void kernel_launch(void* const* d_in, const int* in_sizes, int n_in,
                              void* d_out, int out_size)
{
    const float* x   = (const float*)d_in[0];   // (N, 128)
    const int*   ei  = (const int*)  d_in[1];   // (2, E): row then col
    const float* Wv  = (const float*)d_in[2];   // (128, 128)
    const float* We  = (const float*)d_in[3];   // (128, 128)
    const float* Wu  = (const float*)d_in[4];   // (256, 128)
    const float* bu  = (const float*)d_in[5];   // (128,)
    float* out = (float*)d_out;                 // (N, 128)

    const int E = in_sizes[1] / 2;
    const int N = in_sizes[0] / DD;
    const int* rowp = ei;
    const int* colp = ei + E;

    float* xproj; cudaGetSymbolAddress((void**)&xproj, g_xproj);
    float* esum;  cudaGetSymbolAddress((void**)&esum,  g_esum);
    float* eproj; cudaGetSymbolAddress((void**)&eproj, g_eproj);
    float* nsum;  cudaGetSymbolAddress((void**)&nsum,  g_nsum);
    int* ecnt;    cudaGetSymbolAddress((void**)&ecnt,  g_ecnt);
    int* ncnt;    cudaGetSymbolAddress((void**)&ncnt,  g_ncnt);

    // 1. init accumulators + colmin
    k_init<<<512, 256>>>();
    // 2. col min
    k_colmin<<<512, 256>>>(colp, E);
    // 3. x_proj = x @ W_v
    k_gemm<false, false, false, false><<<(N + 127) / 128, 256>>>(
        x, nullptr, nullptr, nullptr, Wv, nullptr, xproj, N);
    // 4. scatter node -> hyperedge
    k_scatter1<<<4096, 256>>>(rowp, colp, E);
    // 5. e_proj = mean(e_sum) @ W_e
    k_gemm<false, true, false, false><<<(MM + 127) / 128, 256>>>(
        esum, nullptr, ecnt, nullptr, We, nullptr, eproj, MM);
    // 6. scatter hyperedge -> node
    k_scatter2<<<4096, 256>>>(rowp, colp, E);
    // 7. out = relu([x_proj, mean(n_sum)] @ W_u + b_u)
    k_gemm<true, false, true, true><<<(N + 127) / 128, 256>>>(
        xproj, nsum, nullptr, ncnt, Wu, bu, out, N);
}

// round 2
// speedup vs baseline: 1.1340x; 1.1340x over previous
#include <cuda_runtime.h>
#include <cuda_bf16.h>
#include <cstdint>

// Problem constants (from reference)
#define NN 50000   // nodes
#define MM 10000   // hyperedges
#define DD 128     // feature dim (D_IN = D_OUT = 128)

// ---------------- static scratch (no allocations allowed) ----------------
__device__ float g_xproj[NN * DD];   // x @ W_v                 25.6 MB
__device__ float g_xout [NN * DD];   // x @ (W_v @ W_u_top)     25.6 MB
__device__ float g_esum [MM * DD];   // hyperedge sums           5.1 MB
__device__ float g_eproj[MM * DD];   // mean(esum) @ W_eu        5.1 MB
__device__ float g_nsum [NN * DD];   // node sums (output space)25.6 MB
__device__ float g_wvu  [DD * DD];   // W_v @ W_u_top
__device__ float g_weu  [DD * DD];   // W_e @ W_u_bot
__device__ int   g_ecnt [MM];
__device__ int   g_ncnt [NN];
__device__ int   g_colmin;

// ---------------- init: zero accumulators, reset colmin ----------------
__global__ void k_init() {
    int i = blockIdx.x * blockDim.x + threadIdx.x;
    int stride = gridDim.x * blockDim.x;
    for (int j = i; j < NN * DD; j += stride) g_nsum[j] = 0.0f;
    for (int j = i; j < MM * DD; j += stride) g_esum[j] = 0.0f;
    for (int j = i; j < NN; j += stride) g_ncnt[j] = 0;
    for (int j = i; j < MM; j += stride) g_ecnt[j] = 0;
    if (i == 0) g_colmin = 0x7fffffff;
}

// ---------------- col min reduction ----------------
__global__ void k_colmin(const int* __restrict__ col, int E) {
    int v = 0x7fffffff;
    for (int j = blockIdx.x * blockDim.x + threadIdx.x; j < E;
         j += gridDim.x * blockDim.x)
        v = min(v, col[j]);
#pragma unroll
    for (int o = 16; o > 0; o >>= 1) v = min(v, __shfl_down_sync(0xffffffffu, v, o));
    if ((threadIdx.x & 31) == 0) atomicMin(&g_colmin, v);
}

// ---------------- vector float atomic add (sm_90+) ----------------
__device__ __forceinline__ void red_add_v4(float* p, float4 v) {
    asm volatile("red.global.add.v4.f32 [%0], {%1,%2,%3,%4};"
                 :: "l"(p), "f"(v.x), "f"(v.y), "f"(v.z), "f"(v.w)
                 : "memory");
}

// ---------------- scatter 1: node features -> hyperedge sums ----------------
__global__ void k_scatter1(const int* __restrict__ row, const int* __restrict__ col, int E) {
    const int cmin = g_colmin;
    const int lane = threadIdx.x & 31;
    const int warp = (blockIdx.x * blockDim.x + threadIdx.x) >> 5;
    const int nw   = (gridDim.x * blockDim.x) >> 5;
    for (int e = warp; e < E; e += nw) {
        int r = __ldg(&row[e]);
        int c = __ldg(&col[e]) - cmin;
        float4 v = *(const float4*)&g_xproj[(size_t)r * DD + lane * 4];
        red_add_v4(&g_esum[(size_t)c * DD + lane * 4], v);
        if (lane == 0) atomicAdd(&g_ecnt[c], 1);
    }
}

// ---------------- scatter 2: hyperedge features (output space) -> node sums ----------------
__global__ void k_scatter2(const int* __restrict__ row, const int* __restrict__ col, int E) {
    const int cmin = g_colmin;
    const int lane = threadIdx.x & 31;
    const int warp = (blockIdx.x * blockDim.x + threadIdx.x) >> 5;
    const int nw   = (gridDim.x * blockDim.x) >> 5;
    for (int e = warp; e < E; e += nw) {
        int r = __ldg(&row[e]);
        int c = __ldg(&col[e]) - cmin;
        float4 v = *(const float4*)&g_eproj[(size_t)c * DD + lane * 4];
        red_add_v4(&g_nsum[(size_t)r * DD + lane * 4], v);
        if (lane == 0) atomicAdd(&g_ncnt[r], 1);
    }
}

// ---------------- SGEMM body: C[Mrows x 128] = A[Mrows x 128] @ B[128 x 128] ----------------
// SCALE0: A rows scaled by 1/max(cnt0[row],1)  (segment mean fold)
template <bool SCALE0>
__device__ __forceinline__ void gemm_body(
    const float* __restrict__ A0, const int* __restrict__ cnt0,
    const float* __restrict__ Bm, float* __restrict__ C, int Mrows)
{
    __shared__ float As[16][132];  // padded
    __shared__ float Bs[16][128];

    const int tid = threadIdx.x;
    const int ty = tid >> 4;   // 0..15
    const int tx = tid & 15;   // 0..15
    const int rowBase = blockIdx.x * 128;

    float acc[8][8];
#pragma unroll
    for (int i = 0; i < 8; i++)
#pragma unroll
        for (int j = 0; j < 8; j++) acc[i][j] = 0.0f;

    const int aRow = tid >> 2;        // 0..63
    const int aCol = (tid & 3) << 2;  // 0,4,8,12
    const int bRow = tid >> 5;        // 0..7
    const int bCol = (tid & 31) << 2; // 0..124

#pragma unroll
    for (int kb = 0; kb < DD; kb += 16) {
        // load A tile (128 x 16), transposed into As[k][m]
#pragma unroll
        for (int p = 0; p < 2; p++) {
            int r = aRow + p * 64;
            int gr = rowBase + r;
            float4 v = make_float4(0.f, 0.f, 0.f, 0.f);
            if (gr < Mrows) {
                v = *(const float4*)&A0[(size_t)gr * DD + kb + aCol];
                if (SCALE0) {
                    float s = 1.0f / fmaxf((float)__ldg(&cnt0[gr]), 1.0f);
                    v.x *= s; v.y *= s; v.z *= s; v.w *= s;
                }
            }
            As[aCol + 0][r] = v.x;
            As[aCol + 1][r] = v.y;
            As[aCol + 2][r] = v.z;
            As[aCol + 3][r] = v.w;
        }
        // load B tile (16 x 128)
#pragma unroll
        for (int p = 0; p < 2; p++) {
            int kr = bRow + p * 8;
            float4 v = *(const float4*)&Bm[(size_t)(kb + kr) * DD + bCol];
            *(float4*)&Bs[kr][bCol] = v;
        }
        __syncthreads();

#pragma unroll
        for (int k = 0; k < 16; k++) {
            float ar[8], br[8];
            *(float4*)&ar[0] = *(const float4*)&As[k][ty * 8];
            *(float4*)&ar[4] = *(const float4*)&As[k][ty * 8 + 4];
            *(float4*)&br[0] = *(const float4*)&Bs[k][tx * 8];
            *(float4*)&br[4] = *(const float4*)&Bs[k][tx * 8 + 4];
#pragma unroll
            for (int i = 0; i < 8; i++)
#pragma unroll
                for (int j = 0; j < 8; j++)
                    acc[i][j] = fmaf(ar[i], br[j], acc[i][j]);
        }
        __syncthreads();
    }

    // epilogue (plain store)
#pragma unroll
    for (int i = 0; i < 8; i++) {
        int gr = rowBase + ty * 8 + i;
        if (gr < Mrows) {
#pragma unroll
            for (int j = 0; j < 8; j += 4) {
                int gc = tx * 8 + j;
                float4 v = make_float4(acc[i][j], acc[i][j + 1], acc[i][j + 2], acc[i][j + 3]);
                *(float4*)&C[(size_t)gr * DD + gc] = v;
            }
        }
    }
}

// Dual GEMM: blockIdx.y selects config (shared A tiles hit L2)
__global__ void __launch_bounds__(256, 2) k_gemm_dual(
    const float* Aa, const float* Ba, float* Ca,
    const float* Ab, const float* Bb, float* Cb, int Mrows)
{
    if (blockIdx.y == 0) gemm_body<false>(Aa, nullptr, Ba, Ca, Mrows);
    else                 gemm_body<false>(Ab, nullptr, Bb, Cb, Mrows);
}

// Scaled GEMM (segment-mean folded into A loads)
__global__ void __launch_bounds__(256, 2) k_gemm_scale(
    const float* A, const int* cnt, const float* B, float* C, int Mrows)
{
    gemm_body<true>(A, cnt, B, C, Mrows);
}

// ---------------- final fused epilogue: out = relu(xout + nsum/cnt + b) ----------------
__global__ void k_final(const float* __restrict__ bias, float* __restrict__ out, int N) {
    int total = N * (DD / 4);
    for (int i = blockIdx.x * blockDim.x + threadIdx.x; i < total;
         i += gridDim.x * blockDim.x) {
        int r  = i >> 5;        // row
        int cg = i & 31;        // float4 group within row
        float4 a = *(const float4*)&g_xout[(size_t)i * 4];
        float4 s = *(const float4*)&g_nsum[(size_t)i * 4];
        float inv = 1.0f / fmaxf((float)__ldg(&g_ncnt[r]), 1.0f);
        float4 b = *(const float4*)&bias[cg * 4];
        float4 o;
        o.x = fmaxf(fmaf(s.x, inv, a.x) + b.x, 0.0f);
        o.y = fmaxf(fmaf(s.y, inv, a.y) + b.y, 0.0f);
        o.z = fmaxf(fmaf(s.z, inv, a.z) + b.z, 0.0f);
        o.w = fmaxf(fmaf(s.w, inv, a.w) + b.w, 0.0f);
        *(float4*)&out[(size_t)i * 4] = o;
    }
}

// ---------------- launch ----------------
extern "C" void kernel_launch(void* const* d_in, const int* in_sizes, int n_in,
                              void* d_out, int out_size)
{
    const float* x   = (const float*)d_in[0];   // (N, 128)
    const int*   ei  = (const int*)  d_in[1];   // (2, E): row then col
    const float* Wv  = (const float*)d_in[2];   // (128, 128)
    const float* We  = (const float*)d_in[3];   // (128, 128)
    const float* Wu  = (const float*)d_in[4];   // (256, 128)
    const float* bu  = (const float*)d_in[5];   // (128,)
    float* out = (float*)d_out;                 // (N, 128)

    const int E = in_sizes[1] / 2;
    const int N = in_sizes[0] / DD;
    const int* rowp = ei;
    const int* colp = ei + E;

    float* xproj; cudaGetSymbolAddress((void**)&xproj, g_xproj);
    float* xout;  cudaGetSymbolAddress((void**)&xout,  g_xout);
    float* esum;  cudaGetSymbolAddress((void**)&esum,  g_esum);
    float* eproj; cudaGetSymbolAddress((void**)&eproj, g_eproj);
    float* wvu;   cudaGetSymbolAddress((void**)&wvu,   g_wvu);
    float* weu;   cudaGetSymbolAddress((void**)&weu,   g_weu);
    int* ecnt;    cudaGetSymbolAddress((void**)&ecnt,  g_ecnt);
    int* ncnt;    cudaGetSymbolAddress((void**)&ncnt,  g_ncnt);

    // 1. init accumulators + colmin
    k_init<<<512, 256>>>();
    // 2. col min
    k_colmin<<<512, 256>>>(colp, E);
    // 3. weight combos: Wvu = Wv @ Wu[0:128], Weu = We @ Wu[128:256]
    {
        dim3 g(1, 2);
        k_gemm_dual<<<g, 256>>>(Wv, Wu, wvu,
                                We, Wu + DD * DD, weu, DD);
    }
    // 4. big dual GEMM: xproj = x @ Wv ; xout = x @ Wvu
    {
        dim3 g((N + 127) / 128, 2);
        k_gemm_dual<<<g, 256>>>(x, Wv, xproj,
                                x, wvu, xout, N);
    }
    // 5. scatter node -> hyperedge
    k_scatter1<<<4096, 256>>>(rowp, colp, E);
    // 6. eproj = mean(esum) @ Weu   (already in output space)
    k_gemm_scale<<<(MM + 127) / 128, 256>>>(esum, ecnt, weu, eproj, MM);
    // 7. scatter hyperedge -> node (output space)
    k_scatter2<<<4096, 256>>>(rowp, colp, E);
    // 8. out = relu(xout + nsum/cnt + b)
    k_final<<<2048, 256>>>(bu, out, N);
}